// round 2
// baseline (speedup 1.0000x reference)
#include <cuda_runtime.h>

// out[c, i, j, k, l] = tb[c,0,i] * tb[c,1,j] * tb[c,2,k] * tb[c,3,l]
// tb = tensor + bias, shapes (C=2048, 4, 16). Output (C, 16,16,16,16) fp32.
//
// Pure store-bandwidth kernel: 512 MB out, ~1 MB in.
// Persistent grid: 608 CTAs (152 SMs x 4 resident), grid-striding over
// 4096 half-channel units (128 KB each) for ~99.7% load balance.
// Double-buffered smem staging + register prefetch hides input latency.
// __stcs streaming stores (write-once output).

static constexpr int LDIM    = 16;
static constexpr int NFAC    = 4;
static constexpr int THREADS = 256;
static constexpr int GRID    = 608;     // 152 SMs * 4 CTAs
static constexpr int C_CH    = 2048;
static constexpr int N_UNITS = C_CH * 2;   // half-channel units

__global__ __launch_bounds__(THREADS)
void tpe_kernel(const float* __restrict__ tensor,
                const float* __restrict__ bias,
                float4* __restrict__ out)
{
    __shared__ float s[2][NFAC * LDIM];

    const int t = threadIdx.x;

    // Per-thread fixed element-index decomposition (float4 index q = t + 256*it):
    //   l-group lg = q & 3, k = (q>>2) & 15, jlow = (q>>6) & 3  (all from t)
    const int lg   = t & 3;
    const int k    = (t >> 2) & 15;
    const int jlow = (t >> 6) & 3;

    // Prefetch unit 0's channel data into a register.
    int u = blockIdx.x;
    float pre = 0.0f;
    if (t < NFAC * LDIM) {
        const int c = u >> 1;
        const int g = c * (NFAC * LDIM) + t;
        pre = tensor[g] + bias[g];
    }

    int buf = 0;
    for (; u < N_UNITS; u += GRID, buf ^= 1) {
        // Stage prefetched channel into current buffer.
        if (t < NFAC * LDIM) s[buf][t] = pre;
        __syncthreads();

        // Prefetch next unit's channel (latency hidden by the store burst).
        const int un = u + GRID;
        if (un < N_UNITS && t < NFAC * LDIM) {
            const int c = un >> 1;
            const int g = c * (NFAC * LDIM) + t;
            pre = tensor[g] + bias[g];
        }

        const float* sb = s[buf];
        const float  p2 = sb[2 * LDIM + k];
        const float4 v3 = make_float4(sb[3 * LDIM + lg * 4 + 0],
                                      sb[3 * LDIM + lg * 4 + 1],
                                      sb[3 * LDIM + lg * 4 + 2],
                                      sb[3 * LDIM + lg * 4 + 3]);

        const int c     = u >> 1;
        const int ibase = (u & 1) * 8;        // half-channel: i in [ibase, ibase+8)
        float4* ob = out + (size_t)c * 16384 + t;

        #pragma unroll
        for (int ii = 0; ii < 8; ++ii) {
            const int   i  = ibase + ii;
            const float a0 = sb[i] * p2;
            #pragma unroll
            for (int jj = 0; jj < 4; ++jj) {
                const float a  = a0 * sb[LDIM + jlow + (jj << 2)];
                const int   it = (i << 2) + jj;
                float4 v;
                v.x = a * v3.x;
                v.y = a * v3.y;
                v.z = a * v3.z;
                v.w = a * v3.w;
                __stcs(ob + it * 256, v);     // streaming store, evict-first
            }
        }
        // No extra sync needed: next iter writes the OTHER buffer; reuse of
        // this buffer is two syncs away.
    }
}

extern "C" void kernel_launch(void* const* d_in, const int* in_sizes, int n_in,
                              void* d_out, int out_size)
{
    const float* tensor = (const float*)d_in[0];
    const float* bias   = (const float*)d_in[1];
    float4* out         = (float4*)d_out;

    tpe_kernel<<<GRID, THREADS>>>(tensor, bias, out);
}

// round 3
// speedup vs baseline: 1.0496x; 1.0496x over previous
#include <cuda_runtime.h>

// out[c, i, j, k, l] = tb[c,0,i] * tb[c,1,j] * tb[c,2,k] * tb[c,3,l]
// tb = tensor + bias, shapes (C=2048, 4, 16). Output (C, 16,16,16,16) fp32.
//
// Pure store-bandwidth kernel: 512 MB out, ~1 MB in.
// R3 = R1 (one CTA per channel, 2048 CTAs, coalesced STG.128 streams)
//      + __launch_bounds__(256, 8): force regs<=32 so 8 CTAs (64 warps)
//      fit per SM. DRAM% tracked warps-active in R1/R2; max out residency.

static constexpr int LDIM = 16;        // L
static constexpr int NFAC = 4;         // N factors
static constexpr int THREADS = 256;

__global__ __launch_bounds__(THREADS, 8)
void tpe_kernel(const float* __restrict__ tensor,
                const float* __restrict__ bias,
                float4* __restrict__ out)
{
    __shared__ float s[NFAC * LDIM];   // 64 floats: tb rows for this c

    const int c = blockIdx.x;
    const int t = threadIdx.x;

    // Load tb = tensor + bias for this channel into shared.
    if (t < NFAC * LDIM) {
        const int g = c * (NFAC * LDIM) + t;
        s[t] = tensor[g] + bias[g];
    }
    __syncthreads();

    const float* s0 = s;               // factor over i
    const float* s1 = s + LDIM;        // factor over j
    const float* s2 = s + 2 * LDIM;    // factor over k
    const float* s3 = s + 3 * LDIM;    // factor over l

    // float4 linear index within channel: q in [0, 16384), q = t + 256*it.
    //   l-group lg = q & 3       (fixed per thread)
    //   k        = (q>>2) & 15   (fixed per thread)
    //   j        = jlow | ((it&3)<<2),  i = it >> 2
    const int lg   = t & 3;
    const int k    = (t >> 2) & 15;
    const int jlow = (t >> 6) & 3;

    const float p2 = s2[k];
    const float4 v3 = make_float4(s3[lg * 4 + 0], s3[lg * 4 + 1],
                                  s3[lg * 4 + 2], s3[lg * 4 + 3]);

    float4* ob = out + (size_t)c * 16384 + t;

    #pragma unroll
    for (int i = 0; i < 16; ++i) {
        const float a0 = s0[i] * p2;
        #pragma unroll
        for (int jj = 0; jj < 4; ++jj) {
            const float a = a0 * s1[jlow + (jj << 2)];
            const int it = (i << 2) + jj;
            float4 v;
            v.x = a * v3.x;
            v.y = a * v3.y;
            v.z = a * v3.z;
            v.w = a * v3.w;
            ob[it * 256] = v;
        }
    }
}

extern "C" void kernel_launch(void* const* d_in, const int* in_sizes, int n_in,
                              void* d_out, int out_size)
{
    const float* tensor = (const float*)d_in[0];
    const float* bias   = (const float*)d_in[1];
    float4* out         = (float4*)d_out;

    const int C = in_sizes[0] / (NFAC * LDIM);   // 2048

    tpe_kernel<<<C, THREADS>>>(tensor, bias, out);
}

// round 4
// speedup vs baseline: 1.0624x; 1.0122x over previous
#include <cuda_runtime.h>
#include <cstdint>

// out[c, i, j, k, l] = tb[c,0,i] * tb[c,1,j] * tb[c,2,k] * tb[c,3,l]
// tb = tensor + bias, shapes (C=2048, 4, 16). Output (C, 16,16,16,16) fp32.
//
// Pure store-bandwidth kernel: 512 MB out, ~1 MB in.
// R4: 256-bit stores (st.global.v8.b32, sm_100+). Each thread writes one
// 32B float8 per store: halves STG count and L1TEX store wavefronts per
// byte vs STG.128, same perfect 128B-line coalescing (8 lanes per line).

static constexpr int LDIM = 16;
static constexpr int NFAC = 4;
static constexpr int THREADS = 256;

__device__ __forceinline__ void stg_v8(float* p,
                                       float a, float b, float c, float d,
                                       float e, float f, float g, float h)
{
    asm volatile(
        "st.global.v8.b32 [%0], {%1, %2, %3, %4, %5, %6, %7, %8};"
        :: "l"(p),
           "r"(__float_as_uint(a)), "r"(__float_as_uint(b)),
           "r"(__float_as_uint(c)), "r"(__float_as_uint(d)),
           "r"(__float_as_uint(e)), "r"(__float_as_uint(f)),
           "r"(__float_as_uint(g)), "r"(__float_as_uint(h))
        : "memory");
}

__global__ __launch_bounds__(THREADS)
void tpe_kernel(const float* __restrict__ tensor,
                const float* __restrict__ bias,
                float* __restrict__ out)
{
    __shared__ float s[NFAC * LDIM];

    const int c = blockIdx.x;
    const int t = threadIdx.x;

    if (t < NFAC * LDIM) {
        const int g = c * (NFAC * LDIM) + t;
        s[t] = tensor[g] + bias[g];
    }
    __syncthreads();

    const float* s0 = s;               // i
    const float* s1 = s + LDIM;        // j
    const float* s2 = s + 2 * LDIM;    // k
    const float* s3 = s + 3 * LDIM;    // l

    // float8 linear index within channel: r = t + 256*it, it in [0,32).
    // element e = 8r:
    //   l-half lh = r & 1            (fixed per thread; covers l in [8lh, 8lh+8))
    //   k       = (r >> 1) & 15      (fixed per thread)
    //   j       = (r >> 5) & 15 = (t>>5 & 7) | ((it & 1) << 3)
    //   i       = (r >> 9) & 15 = it >> 1
    const int lh   = t & 1;
    const int k    = (t >> 1) & 15;
    const int jlow = (t >> 5) & 7;

    const float p2 = s2[k];
    float v3[8];
    #pragma unroll
    for (int m = 0; m < 8; ++m) v3[m] = s3[lh * 8 + m];

    float* ob = out + (size_t)c * 65536 + (size_t)t * 8;

    #pragma unroll
    for (int i = 0; i < 16; ++i) {
        const float a0 = s0[i] * p2;
        #pragma unroll
        for (int jh = 0; jh < 2; ++jh) {
            const float a  = a0 * s1[jlow + (jh << 3)];
            const int   it = (i << 1) + jh;
            stg_v8(ob + (size_t)it * 2048,
                   a * v3[0], a * v3[1], a * v3[2], a * v3[3],
                   a * v3[4], a * v3[5], a * v3[6], a * v3[7]);
        }
    }
}

extern "C" void kernel_launch(void* const* d_in, const int* in_sizes, int n_in,
                              void* d_out, int out_size)
{
    const float* tensor = (const float*)d_in[0];
    const float* bias   = (const float*)d_in[1];
    float* out          = (float*)d_out;

    const int C = in_sizes[0] / (NFAC * LDIM);   // 2048

    tpe_kernel<<<C, THREADS>>>(tensor, bias, out);
}

// round 5
// speedup vs baseline: 1.0953x; 1.0309x over previous
#include <cuda_runtime.h>
#include <cstdint>

// out[c, i, j, k, l] = tb[c,0,i] * tb[c,1,j] * tb[c,2,k] * tb[c,3,l]
// tb = tensor + bias, shapes (C=2048, 4, 16). Output (C, 16,16,16,16) fp32.
//
// Pure store-bandwidth kernel: 512 MB out, ~1 MB in.
// R5 = R4 (256-bit st.global.v8.b32 stores) + quarter-channel work units:
// grid = 8192 CTAs, each writing a contiguous 64 KB (i in [4q, 4q+4)).
// Rationale: at ~6 resident CTAs/SM a 256KB CTA takes ~34us at its
// fair-share DRAM rate; the 25%-full last wave leaves a multi-us straggler
// tail. 4x smaller grain cuts the quantization error ~4x.

static constexpr int LDIM = 16;
static constexpr int NFAC = 4;
static constexpr int THREADS = 256;

__device__ __forceinline__ void stg_v8(float* p,
                                       float a, float b, float c, float d,
                                       float e, float f, float g, float h)
{
    asm volatile(
        "st.global.v8.b32 [%0], {%1, %2, %3, %4, %5, %6, %7, %8};"
        :: "l"(p),
           "r"(__float_as_uint(a)), "r"(__float_as_uint(b)),
           "r"(__float_as_uint(c)), "r"(__float_as_uint(d)),
           "r"(__float_as_uint(e)), "r"(__float_as_uint(f)),
           "r"(__float_as_uint(g)), "r"(__float_as_uint(h))
        : "memory");
}

__global__ __launch_bounds__(THREADS)
void tpe_kernel(const float* __restrict__ tensor,
                const float* __restrict__ bias,
                float* __restrict__ out)
{
    __shared__ float s[NFAC * LDIM];

    const int b = blockIdx.x;
    const int c = b >> 2;          // channel
    const int q = b & 3;           // quarter: i in [4q, 4q+4)
    const int t = threadIdx.x;

    if (t < NFAC * LDIM) {
        const int g = c * (NFAC * LDIM) + t;
        s[t] = tensor[g] + bias[g];
    }
    __syncthreads();

    const float* s0 = s;               // i
    const float* s1 = s + LDIM;        // j
    const float* s2 = s + 2 * LDIM;    // k
    const float* s3 = s + 3 * LDIM;    // l

    // float8 linear index within channel: r = t + 256*it.
    //   l-half lh = r & 1, k = (r>>1) & 15, jlow = (r>>5) & 7 (from t);
    //   j = jlow | (jh<<3), i = it>>1.
    const int lh   = t & 1;
    const int k    = (t >> 1) & 15;
    const int jlow = (t >> 5) & 7;

    const float p2 = s2[k];
    float v3[8];
    #pragma unroll
    for (int m = 0; m < 8; ++m) v3[m] = s3[lh * 8 + m];

    float* ob = out + (size_t)c * 65536 + (size_t)t * 8;

    #pragma unroll
    for (int ii = 0; ii < 4; ++ii) {
        const int   i  = (q << 2) + ii;
        const float a0 = s0[i] * p2;
        #pragma unroll
        for (int jh = 0; jh < 2; ++jh) {
            const float a  = a0 * s1[jlow + (jh << 3)];
            const int   it = (i << 1) + jh;
            stg_v8(ob + (size_t)it * 2048,
                   a * v3[0], a * v3[1], a * v3[2], a * v3[3],
                   a * v3[4], a * v3[5], a * v3[6], a * v3[7]);
        }
    }
}

extern "C" void kernel_launch(void* const* d_in, const int* in_sizes, int n_in,
                              void* d_out, int out_size)
{
    const float* tensor = (const float*)d_in[0];
    const float* bias   = (const float*)d_in[1];
    float* out          = (float*)d_out;

    const int C = in_sizes[0] / (NFAC * LDIM);   // 2048

    tpe_kernel<<<C * 4, THREADS>>>(tensor, bias, out);
}

// round 6
// speedup vs baseline: 1.1345x; 1.0358x over previous
#include <cuda_runtime.h>
#include <cstdint>

// out[c, i, j, k, l] = tb[c,0,i] * tb[c,1,j] * tb[c,2,k] * tb[c,3,l]
// tb = tensor + bias, shapes (C=2048, 4, 16). Output (C, 16,16,16,16) fp32.
//
// Pure store-bandwidth kernel: 512 MB out, ~1 MB in.
// R6 = R5 with eighth-channel work units: grid = 16384 CTAs, each writing
// a contiguous 32 KB (i in [2q, 2q+2)). Tail-wave quantization loss halves
// again (R5 measured the R4->R5 grain step exactly as predicted).

static constexpr int LDIM = 16;
static constexpr int NFAC = 4;
static constexpr int THREADS = 256;

__device__ __forceinline__ void stg_v8(float* p,
                                       float a, float b, float c, float d,
                                       float e, float f, float g, float h)
{
    asm volatile(
        "st.global.v8.b32 [%0], {%1, %2, %3, %4, %5, %6, %7, %8};"
        :: "l"(p),
           "r"(__float_as_uint(a)), "r"(__float_as_uint(b)),
           "r"(__float_as_uint(c)), "r"(__float_as_uint(d)),
           "r"(__float_as_uint(e)), "r"(__float_as_uint(f)),
           "r"(__float_as_uint(g)), "r"(__float_as_uint(h))
        : "memory");
}

__global__ __launch_bounds__(THREADS)
void tpe_kernel(const float* __restrict__ tensor,
                const float* __restrict__ bias,
                float* __restrict__ out)
{
    __shared__ float s[NFAC * LDIM];

    const int b = blockIdx.x;
    const int c = b >> 3;          // channel
    const int q = b & 7;           // eighth: i in [2q, 2q+2)
    const int t = threadIdx.x;

    if (t < NFAC * LDIM) {
        const int g = c * (NFAC * LDIM) + t;
        s[t] = tensor[g] + bias[g];
    }
    __syncthreads();

    const float* s0 = s;               // i
    const float* s1 = s + LDIM;        // j
    const float* s2 = s + 2 * LDIM;    // k
    const float* s3 = s + 3 * LDIM;    // l

    // float8 linear index within channel: r = t + 256*it.
    //   l-half lh = r & 1, k = (r>>1) & 15, jlow = (r>>5) & 7 (from t);
    //   j = jlow | (jh<<3), i = it>>1.
    const int lh   = t & 1;
    const int k    = (t >> 1) & 15;
    const int jlow = (t >> 5) & 7;

    const float p2 = s2[k];
    float v3[8];
    #pragma unroll
    for (int m = 0; m < 8; ++m) v3[m] = s3[lh * 8 + m];

    float* ob = out + (size_t)c * 65536 + (size_t)t * 8;

    #pragma unroll
    for (int ii = 0; ii < 2; ++ii) {
        const int   i  = (q << 1) + ii;
        const float a0 = s0[i] * p2;
        #pragma unroll
        for (int jh = 0; jh < 2; ++jh) {
            const float a  = a0 * s1[jlow + (jh << 3)];
            const int   it = (i << 1) + jh;
            stg_v8(ob + (size_t)it * 2048,
                   a * v3[0], a * v3[1], a * v3[2], a * v3[3],
                   a * v3[4], a * v3[5], a * v3[6], a * v3[7]);
        }
    }
}

extern "C" void kernel_launch(void* const* d_in, const int* in_sizes, int n_in,
                              void* d_out, int out_size)
{
    const float* tensor = (const float*)d_in[0];
    const float* bias   = (const float*)d_in[1];
    float* out          = (float*)d_out;

    const int C = in_sizes[0] / (NFAC * LDIM);   // 2048

    tpe_kernel<<<C * 8, THREADS>>>(tensor, bias, out);
}

// round 7
// speedup vs baseline: 1.1350x; 1.0004x over previous
#include <cuda_runtime.h>
#include <cstdint>

// out[c, i, j, k, l] = tb[c,0,i] * tb[c,1,j] * tb[c,2,k] * tb[c,3,l]
// tb = tensor + bias, shapes (C=2048, 4, 16). Output (C, 16,16,16,16) fp32.
//
// Pure store-bandwidth kernel: 512 MB out, ~1 MB in.
// R7 = R6 with sixteenth-channel work units: grid = 32768 CTAs, each
// writing a contiguous 16 KB (one i slice). At 8 CTAs/SM this gives a
// 26.9-wave schedule with a 96%-full tail wave — tail-wave quantization
// (the validated R4->R5->R6 mechanism) is essentially eliminated.

static constexpr int LDIM = 16;
static constexpr int NFAC = 4;
static constexpr int THREADS = 256;

__device__ __forceinline__ void stg_v8(float* p,
                                       float a, float b, float c, float d,
                                       float e, float f, float g, float h)
{
    asm volatile(
        "st.global.v8.b32 [%0], {%1, %2, %3, %4, %5, %6, %7, %8};"
        :: "l"(p),
           "r"(__float_as_uint(a)), "r"(__float_as_uint(b)),
           "r"(__float_as_uint(c)), "r"(__float_as_uint(d)),
           "r"(__float_as_uint(e)), "r"(__float_as_uint(f)),
           "r"(__float_as_uint(g)), "r"(__float_as_uint(h))
        : "memory");
}

__global__ __launch_bounds__(THREADS, 8)
void tpe_kernel(const float* __restrict__ tensor,
                const float* __restrict__ bias,
                float* __restrict__ out)
{
    __shared__ float s[NFAC * LDIM];

    const int b = blockIdx.x;
    const int c = b >> 4;          // channel
    const int i = b & 15;          // i slice: this CTA writes out[c, i, :, :, :]
    const int t = threadIdx.x;

    if (t < NFAC * LDIM) {
        const int g = c * (NFAC * LDIM) + t;
        s[t] = tensor[g] + bias[g];
    }
    __syncthreads();

    const float* s0 = s;               // i
    const float* s1 = s + LDIM;        // j
    const float* s2 = s + 2 * LDIM;    // k
    const float* s3 = s + 3 * LDIM;    // l

    // float8 index within the i-slice: r = t + 256*jh, jh in {0,1}.
    //   l-half lh = r & 1, k = (r>>1) & 15, jlow = (r>>5) & 7 (from t);
    //   j = jlow | (jh<<3).
    const int lh   = t & 1;
    const int k    = (t >> 1) & 15;
    const int jlow = (t >> 5) & 7;

    const float p2 = s2[k];
    float v3[8];
    #pragma unroll
    for (int m = 0; m < 8; ++m) v3[m] = s3[lh * 8 + m];

    const float a0 = s0[i] * p2;

    float* ob = out + (size_t)c * 65536 + (size_t)i * 4096 + (size_t)t * 8;

    #pragma unroll
    for (int jh = 0; jh < 2; ++jh) {
        const float a = a0 * s1[jlow + (jh << 3)];
        stg_v8(ob + (size_t)jh * 2048,
               a * v3[0], a * v3[1], a * v3[2], a * v3[3],
               a * v3[4], a * v3[5], a * v3[6], a * v3[7]);
    }
}

extern "C" void kernel_launch(void* const* d_in, const int* in_sizes, int n_in,
                              void* d_out, int out_size)
{
    const float* tensor = (const float*)d_in[0];
    const float* bias   = (const float*)d_in[1];
    float* out          = (float*)d_out;

    const int C = in_sizes[0] / (NFAC * LDIM);   // 2048

    tpe_kernel<<<C * 16, THREADS>>>(tensor, bias, out);
}